// round 8
// baseline (speedup 1.0000x reference)
#include <cuda_runtime.h>
#include <cuda_bf16.h>

#define EPS 1e-6f

// Packed per-face records: 27 floats used, padded to 32 floats = 128 B
// = exactly 4 L2 sectors, 128B-aligned. Corner-major layout:
//   corner k at offset 9k:  pos(3) nrm(3) col(3)
#define MAX_FACES 204800
__device__ __align__(128) float g_packed[(size_t)MAX_FACES * 32];

// 256-bit load (Blackwell LDG.E.256): one full 32B sector per lane.
__device__ __forceinline__ void ldg256(const float* __restrict__ p, float* r) {
    asm volatile("ld.global.nc.v8.f32 {%0,%1,%2,%3,%4,%5,%6,%7}, [%8];"
        : "=f"(r[0]), "=f"(r[1]), "=f"(r[2]), "=f"(r[3]),
          "=f"(r[4]), "=f"(r[5]), "=f"(r[6]), "=f"(r[7])
        : "l"(p));
}

// 3 threads per face: thread t handles corner k = t%3 of face f = t/3.
// faces[t] is a perfectly coalesced load.
__global__ __launch_bounds__(256) void prepack_kernel(
    const int*   __restrict__ faces,
    const float* __restrict__ verts,
    const float* __restrict__ vnorm,
    const float* __restrict__ vcol,
    int F3)
{
    int t = blockIdx.x * blockDim.x + threadIdx.x;
    if (t >= F3) return;
    int f = t / 3;
    int k = t - 3 * f;
    int v = faces[t];

    float* o = g_packed + (size_t)f * 32 + 9 * k;
    o[0] = verts[3*v + 0];
    o[1] = verts[3*v + 1];
    o[2] = verts[3*v + 2];
    o[3] = vnorm[3*v + 0];
    o[4] = vnorm[3*v + 1];
    o[5] = vnorm[3*v + 2];
    o[6] = vcol[3*v + 0];
    o[7] = vcol[3*v + 1];
    o[8] = vcol[3*v + 2];
}

__device__ __forceinline__ void shade_and_store(
    float px, float py, float pz,
    float nx, float ny, float nz,
    float tr, float tg, float tb,
    float lx, float ly, float lz,
    float cx, float cy, float cz,
    const float* __restrict__ l_amb, const float* __restrict__ l_dif,
    const float* __restrict__ l_spec, const float* __restrict__ m_amb,
    const float* __restrict__ m_dif,  const float* __restrict__ m_spec,
    float sh, float4* outp)
{
    // normalize normal
    {
        float nn  = sqrtf(nx*nx + ny*ny + nz*nz);
        float inv = 1.0f / fmaxf(nn, EPS);
        nx *= inv; ny *= inv; nz *= inv;
    }
    // to_light
    float tlx = lx - px, tly = ly - py, tlz = lz - pz;
    {
        float nn  = sqrtf(tlx*tlx + tly*tly + tlz*tlz);
        float inv = 1.0f / fmaxf(nn, EPS);
        tlx *= inv; tly *= inv; tlz *= inv;
    }
    float cosang = nx*tlx + ny*tly + nz*tlz;
    float dmax   = fmaxf(cosang, 0.0f);

    float spec = 0.0f;
    if (cosang > 0.0f) {
        float vx = cx - px, vy = cy - py, vz = cz - pz;
        float nn  = sqrtf(vx*vx + vy*vy + vz*vz);
        float inv = 1.0f / fmaxf(nn, EPS);
        vx *= inv; vy *= inv; vz *= inv;

        float c2 = 2.0f * cosang;
        float rx = c2*nx - tlx;
        float ry = c2*ny - tly;
        float rz = c2*nz - tlz;

        float alpha = fmaxf(vx*rx + vy*ry + vz*rz, 0.0f);
        if (alpha > 0.0f)
            spec = __powf(alpha, sh);
    }

    float cr = (m_amb[0]*l_amb[0] + m_dif[0]*l_dif[0]*dmax) * tr + m_spec[0]*l_spec[0]*spec;
    float cg = (m_amb[1]*l_amb[1] + m_dif[1]*l_dif[1]*dmax) * tg + m_spec[1]*l_spec[1]*spec;
    float cb = (m_amb[2]*l_amb[2] + m_dif[2]*l_dif[2]*dmax) * tb + m_spec[2]*l_spec[2]*spec;

    *outp = make_float4(cr, cg, cb, 1.0f);
}

// Fast path: 4x 256-bit loads from a single 128B face record.
__global__ __launch_bounds__(256) void shade_packed_kernel(
    const int*   __restrict__ p2f,
    const float* __restrict__ bary,
    const float* __restrict__ lloc,
    const float* __restrict__ l_amb,
    const float* __restrict__ l_dif,
    const float* __restrict__ l_spec,
    const float* __restrict__ m_amb,
    const float* __restrict__ m_dif,
    const float* __restrict__ m_spec,
    const float* __restrict__ shin,
    const float* __restrict__ cam,
    const float* __restrict__ bg,
    float4*      __restrict__ out,
    int HW)
{
    int pix = blockIdx.x * blockDim.x + threadIdx.x;
    if (pix >= HW) return;
    int nb = blockIdx.y;
    int i  = nb * HW + pix;

    int f = p2f[i];
    if (f < 0) {
        out[i] = make_float4(bg[0], bg[1], bg[2], 0.0f);
        return;
    }

    float b0 = bary[3*i + 0];
    float b1 = bary[3*i + 1];
    float b2 = bary[3*i + 2];

    const float* q = g_packed + (size_t)f * 32;
    float a[32];
    ldg256(q +  0, a +  0);
    ldg256(q +  8, a +  8);
    ldg256(q + 16, a + 16);
    ldg256(q + 24, a + 24);

    // corner-major: corner k at 9k -> pos(3) nrm(3) col(3)
    float px = b0*a[0] + b1*a[ 9] + b2*a[18];
    float py = b0*a[1] + b1*a[10] + b2*a[19];
    float pz = b0*a[2] + b1*a[11] + b2*a[20];

    float nx = b0*a[3] + b1*a[12] + b2*a[21];
    float ny = b0*a[4] + b1*a[13] + b2*a[22];
    float nz = b0*a[5] + b1*a[14] + b2*a[23];

    float tr = b0*a[6] + b1*a[15] + b2*a[24];
    float tg = b0*a[7] + b1*a[16] + b2*a[25];
    float tb = b0*a[8] + b1*a[17] + b2*a[26];

    shade_and_store(px, py, pz, nx, ny, nz, tr, tg, tb,
                    lloc[3*nb+0], lloc[3*nb+1], lloc[3*nb+2],
                    cam[3*nb+0],  cam[3*nb+1],  cam[3*nb+2],
                    l_amb, l_dif, l_spec, m_amb, m_dif, m_spec,
                    shin[0], &out[i]);
}

// Fallback path (F > MAX_FACES): direct gathers.
__global__ __launch_bounds__(256) void shade_direct_kernel(
    const int*   __restrict__ p2f,
    const float* __restrict__ bary,
    const float* __restrict__ verts,
    const float* __restrict__ vnorm,
    const float* __restrict__ vcol,
    const int*   __restrict__ faces,
    const float* __restrict__ lloc,
    const float* __restrict__ l_amb,
    const float* __restrict__ l_dif,
    const float* __restrict__ l_spec,
    const float* __restrict__ m_amb,
    const float* __restrict__ m_dif,
    const float* __restrict__ m_spec,
    const float* __restrict__ shin,
    const float* __restrict__ cam,
    const float* __restrict__ bg,
    float4*      __restrict__ out,
    int HW)
{
    int pix = blockIdx.x * blockDim.x + threadIdx.x;
    if (pix >= HW) return;
    int nb = blockIdx.y;
    int i  = nb * HW + pix;

    int f = p2f[i];
    if (f < 0) {
        out[i] = make_float4(bg[0], bg[1], bg[2], 0.0f);
        return;
    }

    float b0 = bary[3*i + 0];
    float b1 = bary[3*i + 1];
    float b2 = bary[3*i + 2];

    int v0 = faces[3*f + 0];
    int v1 = faces[3*f + 1];
    int v2 = faces[3*f + 2];

    float px = b0*verts[3*v0+0] + b1*verts[3*v1+0] + b2*verts[3*v2+0];
    float py = b0*verts[3*v0+1] + b1*verts[3*v1+1] + b2*verts[3*v2+1];
    float pz = b0*verts[3*v0+2] + b1*verts[3*v1+2] + b2*verts[3*v2+2];

    float nx = b0*vnorm[3*v0+0] + b1*vnorm[3*v1+0] + b2*vnorm[3*v2+0];
    float ny = b0*vnorm[3*v0+1] + b1*vnorm[3*v1+1] + b2*vnorm[3*v2+1];
    float nz = b0*vnorm[3*v0+2] + b1*vnorm[3*v1+2] + b2*vnorm[3*v2+2];

    float tr = b0*vcol[3*v0+0] + b1*vcol[3*v1+0] + b2*vcol[3*v2+0];
    float tg = b0*vcol[3*v0+1] + b1*vcol[3*v1+1] + b2*vcol[3*v2+1];
    float tb = b0*vcol[3*v0+2] + b1*vcol[3*v1+2] + b2*vcol[3*v2+2];

    shade_and_store(px, py, pz, nx, ny, nz, tr, tg, tb,
                    lloc[3*nb+0], lloc[3*nb+1], lloc[3*nb+2],
                    cam[3*nb+0],  cam[3*nb+1],  cam[3*nb+2],
                    l_amb, l_dif, l_spec, m_amb, m_dif, m_spec,
                    shin[0], &out[i]);
}

extern "C" void kernel_launch(void* const* d_in, const int* in_sizes, int n_in,
                              void* d_out, int out_size) {
    const int*   p2f    = (const int*)  d_in[0];
    const float* bary   = (const float*)d_in[1];
    const float* verts  = (const float*)d_in[2];
    const float* vnorm  = (const float*)d_in[3];
    const float* vcol   = (const float*)d_in[4];
    const int*   faces  = (const int*)  d_in[5];
    const float* lloc   = (const float*)d_in[6];
    const float* l_amb  = (const float*)d_in[7];
    const float* l_dif  = (const float*)d_in[8];
    const float* l_spec = (const float*)d_in[9];
    const float* m_amb  = (const float*)d_in[10];
    const float* m_dif  = (const float*)d_in[11];
    const float* m_spec = (const float*)d_in[12];
    const float* shin   = (const float*)d_in[13];
    const float* cam    = (const float*)d_in[14];
    const float* bg     = (const float*)d_in[15];

    int total = in_sizes[0];          // N*H*W*K, K=1
    int N     = in_sizes[6] / 3;      // light_location is (N,3)
    int HW    = total / N;
    int F3    = in_sizes[5];          // 3*F
    int F     = F3 / 3;

    int threads = 256;
    dim3 grid((HW + threads - 1) / threads, N);

    if (F <= MAX_FACES) {
        prepack_kernel<<<(F3 + threads - 1) / threads, threads>>>(
            faces, verts, vnorm, vcol, F3);
        shade_packed_kernel<<<grid, threads>>>(
            p2f, bary, lloc,
            l_amb, l_dif, l_spec, m_amb, m_dif, m_spec, shin, cam, bg,
            (float4*)d_out, HW);
    } else {
        shade_direct_kernel<<<grid, threads>>>(
            p2f, bary, verts, vnorm, vcol, faces, lloc,
            l_amb, l_dif, l_spec, m_amb, m_dif, m_spec, shin, cam, bg,
            (float4*)d_out, HW);
    }
}

// round 9
// speedup vs baseline: 1.2912x; 1.2912x over previous
#include <cuda_runtime.h>
#include <cuda_bf16.h>

#define EPS 1e-6f

// ---------------------------------------------------------------------------
// Scratch (static __device__ arrays; no allocation).
// g_vtx:    per-vertex record, 16 floats (64 B, 2 sectors): pos(3) nrm(3) col(3) pad(7)
// g_packed: per-face record, 32 floats (128 B = 1 cache line): corner-major
//           corner k at offset 9k: pos(3) nrm(3) col(3); floats 27..31 pad
// ---------------------------------------------------------------------------
#define MAX_FACES 204800
#define MAX_VERTS 131072
__device__ __align__(128) float g_packed[(size_t)MAX_FACES * 32];
__device__ __align__(128) float g_vtx[(size_t)MAX_VERTS * 16];

// 256-bit load (Blackwell LDG.E.256). Requires 32B-aligned address.
__device__ __forceinline__ void ldg256(const float* __restrict__ p, float* r) {
    asm volatile("ld.global.nc.v8.f32 {%0,%1,%2,%3,%4,%5,%6,%7}, [%8];"
        : "=f"(r[0]), "=f"(r[1]), "=f"(r[2]), "=f"(r[3]),
          "=f"(r[4]), "=f"(r[5]), "=f"(r[6]), "=f"(r[7])
        : "l"(p));
}

// ---------------------------------------------------------------------------
// Stage 1: pack vertices (fully coalesced streaming)
// ---------------------------------------------------------------------------
__global__ __launch_bounds__(256) void pack_verts_kernel(
    const float* __restrict__ verts,
    const float* __restrict__ vnorm,
    const float* __restrict__ vcol,
    int V)
{
    int v = blockIdx.x * blockDim.x + threadIdx.x;
    if (v >= V) return;
    float px = verts[3*v+0], py = verts[3*v+1], pz = verts[3*v+2];
    float nx = vnorm[3*v+0], ny = vnorm[3*v+1], nz = vnorm[3*v+2];
    float cx = vcol [3*v+0], cy = vcol [3*v+1], cz = vcol [3*v+2];
    float4* o = (float4*)(g_vtx + (size_t)v * 16);
    o[0] = make_float4(px, py, pz, nx);
    o[1] = make_float4(ny, nz, cx, cy);
    o[2] = make_float4(cz, 0.f, 0.f, 0.f);
}

// ---------------------------------------------------------------------------
// Stage 2: pack faces. One thread per face, 6x LDG.256 from vertex records,
// output via smem staging -> fully coalesced 16B-chunk stores.
// smem stride 36 floats (144B, 16B-aligned, conflict-free per quarter-warp).
// ---------------------------------------------------------------------------
__global__ __launch_bounds__(256) void pack_faces_kernel(
    const int* __restrict__ faces,
    int F)
{
    __shared__ float s[256 * 36];
    int f0 = blockIdx.x * 256;
    int f  = f0 + threadIdx.x;

    float r[32];
    if (f < F) {
        int v0 = faces[3*f + 0];
        int v1 = faces[3*f + 1];
        int v2 = faces[3*f + 2];
        float t[16];
        ldg256(g_vtx + (size_t)v0*16,     t);
        ldg256(g_vtx + (size_t)v0*16 + 8, t + 8);
        #pragma unroll
        for (int k = 0; k < 9; k++) r[k] = t[k];
        ldg256(g_vtx + (size_t)v1*16,     t);
        ldg256(g_vtx + (size_t)v1*16 + 8, t + 8);
        #pragma unroll
        for (int k = 0; k < 9; k++) r[9 + k] = t[k];
        ldg256(g_vtx + (size_t)v2*16,     t);
        ldg256(g_vtx + (size_t)v2*16 + 8, t + 8);
        #pragma unroll
        for (int k = 0; k < 9; k++) r[18 + k] = t[k];
        #pragma unroll
        for (int k = 27; k < 32; k++) r[k] = 0.0f;
    } else {
        #pragma unroll
        for (int k = 0; k < 32; k++) r[k] = 0.0f;
    }

    // Stage into smem (8x STS.128, conflict-free)
    #pragma unroll
    for (int j = 0; j < 8; j++)
        *(float4*)(s + threadIdx.x * 36 + 4*j) =
            make_float4(r[4*j+0], r[4*j+1], r[4*j+2], r[4*j+3]);
    __syncthreads();

    // Coalesced copy: 2048 chunks of 16B per block
    float4* gout = (float4*)(g_packed + (size_t)f0 * 32);
    #pragma unroll
    for (int p = 0; p < 8; p++) {
        int c   = p * 256 + threadIdx.x;   // 16B chunk index in block
        int rec = c >> 3;
        int off = c & 7;
        gout[c] = *(const float4*)(s + rec * 36 + 4 * off);
    }
}

// ---------------------------------------------------------------------------
// Shading math
// ---------------------------------------------------------------------------
__device__ __forceinline__ void shade_and_store(
    float px, float py, float pz,
    float nx, float ny, float nz,
    float tr, float tg, float tb,
    float lx, float ly, float lz,
    float cx, float cy, float cz,
    const float* __restrict__ l_amb, const float* __restrict__ l_dif,
    const float* __restrict__ l_spec, const float* __restrict__ m_amb,
    const float* __restrict__ m_dif,  const float* __restrict__ m_spec,
    float sh, float4* outp)
{
    {
        float nn  = sqrtf(nx*nx + ny*ny + nz*nz);
        float inv = 1.0f / fmaxf(nn, EPS);
        nx *= inv; ny *= inv; nz *= inv;
    }
    float tlx = lx - px, tly = ly - py, tlz = lz - pz;
    {
        float nn  = sqrtf(tlx*tlx + tly*tly + tlz*tlz);
        float inv = 1.0f / fmaxf(nn, EPS);
        tlx *= inv; tly *= inv; tlz *= inv;
    }
    float cosang = nx*tlx + ny*tly + nz*tlz;
    float dmax   = fmaxf(cosang, 0.0f);

    float spec = 0.0f;
    if (cosang > 0.0f) {
        float vx = cx - px, vy = cy - py, vz = cz - pz;
        float nn  = sqrtf(vx*vx + vy*vy + vz*vz);
        float inv = 1.0f / fmaxf(nn, EPS);
        vx *= inv; vy *= inv; vz *= inv;

        float c2 = 2.0f * cosang;
        float rx = c2*nx - tlx;
        float ry = c2*ny - tly;
        float rz = c2*nz - tlz;

        float alpha = fmaxf(vx*rx + vy*ry + vz*rz, 0.0f);
        if (alpha > 0.0f)
            spec = __powf(alpha, sh);
    }

    float cr = (m_amb[0]*l_amb[0] + m_dif[0]*l_dif[0]*dmax) * tr + m_spec[0]*l_spec[0]*spec;
    float cg = (m_amb[1]*l_amb[1] + m_dif[1]*l_dif[1]*dmax) * tg + m_spec[1]*l_spec[1]*spec;
    float cb = (m_amb[2]*l_amb[2] + m_dif[2]*l_dif[2]*dmax) * tb + m_spec[2]*l_spec[2]*spec;

    *outp = make_float4(cr, cg, cb, 1.0f);
}

// ---------------------------------------------------------------------------
// Shade: warp-cooperative gather. Thread t loads sector (t&3) of record
// (t>>2) per pass -> 4 lanes share each 128B line -> 8 wavefronts/LDG.256.
// ---------------------------------------------------------------------------
__global__ __launch_bounds__(256) void shade_packed_kernel(
    const int*   __restrict__ p2f,
    const float* __restrict__ bary,
    const float* __restrict__ lloc,
    const float* __restrict__ l_amb,
    const float* __restrict__ l_dif,
    const float* __restrict__ l_spec,
    const float* __restrict__ m_amb,
    const float* __restrict__ m_dif,
    const float* __restrict__ m_spec,
    const float* __restrict__ shin,
    const float* __restrict__ cam,
    const float* __restrict__ bg,
    float4*      __restrict__ out,
    int HW)
{
    __shared__ float s[256 * 36];
    __shared__ int   sface[256];

    int tid = threadIdx.x;
    int pix = blockIdx.x * 256 + tid;
    int nb  = blockIdx.y;
    int i   = nb * HW + pix;

    int f = -1;
    float b0 = 0.f, b1 = 0.f, b2 = 0.f;
    if (pix < HW) {
        f  = p2f[i];
        b0 = bary[3*i + 0];
        b1 = bary[3*i + 1];
        b2 = bary[3*i + 2];
    }
    sface[tid] = (f < 0) ? 0 : f;
    __syncthreads();

    // Cooperative staging: 4 passes x 64 records, 4 lanes per record
    #pragma unroll
    for (int p = 0; p < 4; p++) {
        int slot = p * 64 + (tid >> 2);
        int sec  = tid & 3;
        int rec  = sface[slot];
        float t[8];
        ldg256(g_packed + (size_t)rec * 32 + sec * 8, t);
        float* d = s + slot * 36 + sec * 8;
        *(float4*)(d + 0) = make_float4(t[0], t[1], t[2], t[3]);
        *(float4*)(d + 4) = make_float4(t[4], t[5], t[6], t[7]);
    }
    __syncthreads();

    if (pix >= HW) return;

    if (f < 0) {
        out[i] = make_float4(bg[0], bg[1], bg[2], 0.0f);
        return;
    }

    // Read my record back (7x LDS.128, conflict-free per quarter-warp)
    float a[28];
    #pragma unroll
    for (int j = 0; j < 7; j++) {
        float4 t = *(const float4*)(s + tid * 36 + 4*j);
        a[4*j+0] = t.x; a[4*j+1] = t.y; a[4*j+2] = t.z; a[4*j+3] = t.w;
    }

    float px = b0*a[0] + b1*a[ 9] + b2*a[18];
    float py = b0*a[1] + b1*a[10] + b2*a[19];
    float pz = b0*a[2] + b1*a[11] + b2*a[20];

    float nx = b0*a[3] + b1*a[12] + b2*a[21];
    float ny = b0*a[4] + b1*a[13] + b2*a[22];
    float nz = b0*a[5] + b1*a[14] + b2*a[23];

    float tr = b0*a[6] + b1*a[15] + b2*a[24];
    float tg = b0*a[7] + b1*a[16] + b2*a[25];
    float tb = b0*a[8] + b1*a[17] + b2*a[26];

    shade_and_store(px, py, pz, nx, ny, nz, tr, tg, tb,
                    lloc[3*nb+0], lloc[3*nb+1], lloc[3*nb+2],
                    cam[3*nb+0],  cam[3*nb+1],  cam[3*nb+2],
                    l_amb, l_dif, l_spec, m_amb, m_dif, m_spec,
                    shin[0], &out[i]);
}

// ---------------------------------------------------------------------------
// Fallback path (mesh exceeds static scratch): direct gathers.
// ---------------------------------------------------------------------------
__global__ __launch_bounds__(256) void shade_direct_kernel(
    const int*   __restrict__ p2f,
    const float* __restrict__ bary,
    const float* __restrict__ verts,
    const float* __restrict__ vnorm,
    const float* __restrict__ vcol,
    const int*   __restrict__ faces,
    const float* __restrict__ lloc,
    const float* __restrict__ l_amb,
    const float* __restrict__ l_dif,
    const float* __restrict__ l_spec,
    const float* __restrict__ m_amb,
    const float* __restrict__ m_dif,
    const float* __restrict__ m_spec,
    const float* __restrict__ shin,
    const float* __restrict__ cam,
    const float* __restrict__ bg,
    float4*      __restrict__ out,
    int HW)
{
    int pix = blockIdx.x * blockDim.x + threadIdx.x;
    if (pix >= HW) return;
    int nb = blockIdx.y;
    int i  = nb * HW + pix;

    int f = p2f[i];
    if (f < 0) {
        out[i] = make_float4(bg[0], bg[1], bg[2], 0.0f);
        return;
    }

    float b0 = bary[3*i + 0];
    float b1 = bary[3*i + 1];
    float b2 = bary[3*i + 2];

    int v0 = faces[3*f + 0];
    int v1 = faces[3*f + 1];
    int v2 = faces[3*f + 2];

    float px = b0*verts[3*v0+0] + b1*verts[3*v1+0] + b2*verts[3*v2+0];
    float py = b0*verts[3*v0+1] + b1*verts[3*v1+1] + b2*verts[3*v2+1];
    float pz = b0*verts[3*v0+2] + b1*verts[3*v1+2] + b2*verts[3*v2+2];

    float nx = b0*vnorm[3*v0+0] + b1*vnorm[3*v1+0] + b2*vnorm[3*v2+0];
    float ny = b0*vnorm[3*v0+1] + b1*vnorm[3*v1+1] + b2*vnorm[3*v2+1];
    float nz = b0*vnorm[3*v0+2] + b1*vnorm[3*v1+2] + b2*vnorm[3*v2+2];

    float tr = b0*vcol[3*v0+0] + b1*vcol[3*v1+0] + b2*vcol[3*v2+0];
    float tg = b0*vcol[3*v0+1] + b1*vcol[3*v1+1] + b2*vcol[3*v2+1];
    float tb = b0*vcol[3*v0+2] + b1*vcol[3*v1+2] + b2*vcol[3*v2+2];

    shade_and_store(px, py, pz, nx, ny, nz, tr, tg, tb,
                    lloc[3*nb+0], lloc[3*nb+1], lloc[3*nb+2],
                    cam[3*nb+0],  cam[3*nb+1],  cam[3*nb+2],
                    l_amb, l_dif, l_spec, m_amb, m_dif, m_spec,
                    shin[0], &out[i]);
}

extern "C" void kernel_launch(void* const* d_in, const int* in_sizes, int n_in,
                              void* d_out, int out_size) {
    const int*   p2f    = (const int*)  d_in[0];
    const float* bary   = (const float*)d_in[1];
    const float* verts  = (const float*)d_in[2];
    const float* vnorm  = (const float*)d_in[3];
    const float* vcol   = (const float*)d_in[4];
    const int*   faces  = (const int*)  d_in[5];
    const float* lloc   = (const float*)d_in[6];
    const float* l_amb  = (const float*)d_in[7];
    const float* l_dif  = (const float*)d_in[8];
    const float* l_spec = (const float*)d_in[9];
    const float* m_amb  = (const float*)d_in[10];
    const float* m_dif  = (const float*)d_in[11];
    const float* m_spec = (const float*)d_in[12];
    const float* shin   = (const float*)d_in[13];
    const float* cam    = (const float*)d_in[14];
    const float* bg     = (const float*)d_in[15];

    int total = in_sizes[0];          // N*H*W*K, K=1
    int N     = in_sizes[6] / 3;      // light_location is (N,3)
    int HW    = total / N;
    int F     = in_sizes[5] / 3;      // faces is (F,3)
    int V     = in_sizes[2] / 3;      // verts is (V,3)

    int threads = 256;
    dim3 grid((HW + threads - 1) / threads, N);

    if (F <= MAX_FACES && V <= MAX_VERTS) {
        pack_verts_kernel<<<(V + threads - 1) / threads, threads>>>(
            verts, vnorm, vcol, V);
        pack_faces_kernel<<<(F + threads - 1) / threads, threads>>>(faces, F);
        shade_packed_kernel<<<grid, threads>>>(
            p2f, bary, lloc,
            l_amb, l_dif, l_spec, m_amb, m_dif, m_spec, shin, cam, bg,
            (float4*)d_out, HW);
    } else {
        shade_direct_kernel<<<grid, threads>>>(
            p2f, bary, verts, vnorm, vcol, faces, lloc,
            l_amb, l_dif, l_spec, m_amb, m_dif, m_spec, shin, cam, bg,
            (float4*)d_out, HW);
    }
}

// round 10
// speedup vs baseline: 1.3998x; 1.0841x over previous
#include <cuda_runtime.h>
#include <cuda_bf16.h>

#define EPS 1e-6f

// ---------------------------------------------------------------------------
// Scratch (static __device__ arrays; no allocation).
// g_vtx:    per-vertex record, 16 floats (64 B): pos(3) nrm(3) col(3) pad(7)
// g_packed: per-face record, 32 floats (128 B = 1 line): corner-major,
//           corner k at offset 9k: pos(3) nrm(3) col(3); floats 27..31 pad
// ---------------------------------------------------------------------------
#define MAX_FACES 204800
#define MAX_VERTS 131072
__device__ __align__(128) float g_packed[(size_t)MAX_FACES * 32];
__device__ __align__(128) float g_vtx[(size_t)MAX_VERTS * 16];

// 256-bit load (Blackwell LDG.E.256). Requires 32B-aligned address.
__device__ __forceinline__ void ldg256(const float* __restrict__ p, float* r) {
    asm volatile("ld.global.nc.v8.f32 {%0,%1,%2,%3,%4,%5,%6,%7}, [%8];"
        : "=f"(r[0]), "=f"(r[1]), "=f"(r[2]), "=f"(r[3]),
          "=f"(r[4]), "=f"(r[5]), "=f"(r[6]), "=f"(r[7])
        : "l"(p));
}

// ---------------------------------------------------------------------------
// Stage 1: pack vertices. Block stages 256 vertices' worth of each attribute
// array via coalesced float4 loads into smem, then writes 64B records.
// ---------------------------------------------------------------------------
__global__ __launch_bounds__(256) void pack_verts_kernel(
    const float* __restrict__ verts,
    const float* __restrict__ vnorm,
    const float* __restrict__ vcol,
    int V)
{
    __shared__ float sp[768], sn[768], sc[768];
    int t  = threadIdx.x;
    int v0 = blockIdx.x * 256;

    if (v0 + 256 <= V) {
        // full block: 3 arrays x 192 float4 = 576 chunks over 256 threads
        const float4* vp = (const float4*)(verts + (size_t)v0 * 3);
        const float4* np = (const float4*)(vnorm + (size_t)v0 * 3);
        const float4* cp = (const float4*)(vcol  + (size_t)v0 * 3);
        #pragma unroll
        for (int c = t; c < 576; c += 256) {
            int arr = c / 192;
            int idx = c - arr * 192;
            float4 val = (arr == 0) ? vp[idx] : (arr == 1) ? np[idx] : cp[idx];
            float* dst = (arr == 0) ? sp : (arr == 1) ? sn : sc;
            *(float4*)(dst + 4 * idx) = val;
        }
        __syncthreads();

        int v = v0 + t;
        float4* o = (float4*)(g_vtx + (size_t)v * 16);
        o[0] = make_float4(sp[3*t+0], sp[3*t+1], sp[3*t+2], sn[3*t+0]);
        o[1] = make_float4(sn[3*t+1], sn[3*t+2], sc[3*t+0], sc[3*t+1]);
        o[2] = make_float4(sc[3*t+2], 0.f, 0.f, 0.f);
    } else {
        // tail block: scalar path
        int v = v0 + t;
        if (v >= V) return;
        float4* o = (float4*)(g_vtx + (size_t)v * 16);
        o[0] = make_float4(verts[3*v+0], verts[3*v+1], verts[3*v+2], vnorm[3*v+0]);
        o[1] = make_float4(vnorm[3*v+1], vnorm[3*v+2], vcol[3*v+0], vcol[3*v+1]);
        o[2] = make_float4(vcol[3*v+2], 0.f, 0.f, 0.f);
    }
}

// ---------------------------------------------------------------------------
// Stage 2: pack faces. One thread per face, 6x LDG.256 from vertex records,
// output via smem staging -> fully coalesced 16B-chunk stores.
// ---------------------------------------------------------------------------
__global__ __launch_bounds__(256) void pack_faces_kernel(
    const int* __restrict__ faces,
    int F)
{
    __shared__ float s[256 * 36];
    int f0 = blockIdx.x * 256;
    int f  = f0 + threadIdx.x;

    float r[32];
    if (f < F) {
        int v0 = faces[3*f + 0];
        int v1 = faces[3*f + 1];
        int v2 = faces[3*f + 2];
        float t[16];
        ldg256(g_vtx + (size_t)v0*16,     t);
        ldg256(g_vtx + (size_t)v0*16 + 8, t + 8);
        #pragma unroll
        for (int k = 0; k < 9; k++) r[k] = t[k];
        ldg256(g_vtx + (size_t)v1*16,     t);
        ldg256(g_vtx + (size_t)v1*16 + 8, t + 8);
        #pragma unroll
        for (int k = 0; k < 9; k++) r[9 + k] = t[k];
        ldg256(g_vtx + (size_t)v2*16,     t);
        ldg256(g_vtx + (size_t)v2*16 + 8, t + 8);
        #pragma unroll
        for (int k = 0; k < 9; k++) r[18 + k] = t[k];
        #pragma unroll
        for (int k = 27; k < 32; k++) r[k] = 0.0f;
    } else {
        #pragma unroll
        for (int k = 0; k < 32; k++) r[k] = 0.0f;
    }

    #pragma unroll
    for (int j = 0; j < 8; j++)
        *(float4*)(s + threadIdx.x * 36 + 4*j) =
            make_float4(r[4*j+0], r[4*j+1], r[4*j+2], r[4*j+3]);
    __syncthreads();

    float4* gout = (float4*)(g_packed + (size_t)f0 * 32);
    #pragma unroll
    for (int p = 0; p < 8; p++) {
        int c   = p * 256 + threadIdx.x;
        int rec = c >> 3;
        int off = c & 7;
        gout[c] = *(const float4*)(s + rec * 36 + 4 * off);
    }
}

// ---------------------------------------------------------------------------
// Shading math
// ---------------------------------------------------------------------------
__device__ __forceinline__ void shade_and_store(
    float px, float py, float pz,
    float nx, float ny, float nz,
    float tr, float tg, float tb,
    float lx, float ly, float lz,
    float cx, float cy, float cz,
    const float* __restrict__ l_amb, const float* __restrict__ l_dif,
    const float* __restrict__ l_spec, const float* __restrict__ m_amb,
    const float* __restrict__ m_dif,  const float* __restrict__ m_spec,
    float sh, float4* outp)
{
    {
        float nn  = sqrtf(nx*nx + ny*ny + nz*nz);
        float inv = 1.0f / fmaxf(nn, EPS);
        nx *= inv; ny *= inv; nz *= inv;
    }
    float tlx = lx - px, tly = ly - py, tlz = lz - pz;
    {
        float nn  = sqrtf(tlx*tlx + tly*tly + tlz*tlz);
        float inv = 1.0f / fmaxf(nn, EPS);
        tlx *= inv; tly *= inv; tlz *= inv;
    }
    float cosang = nx*tlx + ny*tly + nz*tlz;
    float dmax   = fmaxf(cosang, 0.0f);

    float spec = 0.0f;
    if (cosang > 0.0f) {
        float vx = cx - px, vy = cy - py, vz = cz - pz;
        float nn  = sqrtf(vx*vx + vy*vy + vz*vz);
        float inv = 1.0f / fmaxf(nn, EPS);
        vx *= inv; vy *= inv; vz *= inv;

        float c2 = 2.0f * cosang;
        float rx = c2*nx - tlx;
        float ry = c2*ny - tly;
        float rz = c2*nz - tlz;

        float alpha = fmaxf(vx*rx + vy*ry + vz*rz, 0.0f);
        if (alpha > 0.0f)
            spec = __powf(alpha, sh);
    }

    float cr = (m_amb[0]*l_amb[0] + m_dif[0]*l_dif[0]*dmax) * tr + m_spec[0]*l_spec[0]*spec;
    float cg = (m_amb[1]*l_amb[1] + m_dif[1]*l_dif[1]*dmax) * tg + m_spec[1]*l_spec[1]*spec;
    float cb = (m_amb[2]*l_amb[2] + m_dif[2]*l_dif[2]*dmax) * tb + m_spec[2]*l_spec[2]*spec;

    *outp = make_float4(cr, cg, cb, 1.0f);
}

// ---------------------------------------------------------------------------
// Shade: WARP-LOCAL cooperative gather. Each warp stages its own 32 records
// (4 lanes x LDG.256 per record, face idx via shfl) into a private smem
// slice; only __syncwarp() needed. 48 independent warps/SM hide L2 latency.
// ---------------------------------------------------------------------------
__global__ __launch_bounds__(256) void shade_packed_kernel(
    const int*   __restrict__ p2f,
    const float* __restrict__ bary,
    const float* __restrict__ lloc,
    const float* __restrict__ l_amb,
    const float* __restrict__ l_dif,
    const float* __restrict__ l_spec,
    const float* __restrict__ m_amb,
    const float* __restrict__ m_dif,
    const float* __restrict__ m_spec,
    const float* __restrict__ shin,
    const float* __restrict__ cam,
    const float* __restrict__ bg,
    float4*      __restrict__ out,
    int HW)
{
    __shared__ float s[256 * 36];

    int tid  = threadIdx.x;
    int lane = tid & 31;
    int pix  = blockIdx.x * 256 + tid;
    int nb   = blockIdx.y;
    int i    = nb * HW + pix;

    int f = -1;
    float b0 = 0.f, b1 = 0.f, b2 = 0.f;
    bool valid = pix < HW;
    if (valid) {
        f  = p2f[i];
        b0 = bary[3*i + 0];
        b1 = bary[3*i + 1];
        b2 = bary[3*i + 2];
    }
    int frec = (f < 0) ? 0 : f;

    float* ws = s + (tid >> 5) * (32 * 36);   // this warp's smem slice

    // 4 passes: 8 records per pass, 4 lanes per record (one sector each)
    #pragma unroll
    for (int p = 0; p < 4; p++) {
        int slot = p * 8 + (lane >> 2);                     // record slot 0..31
        int rec  = __shfl_sync(0xffffffffu, frec, slot);    // owner's face
        int sec  = lane & 3;
        float t[8];
        ldg256(g_packed + (size_t)rec * 32 + sec * 8, t);
        float* d = ws + slot * 36 + sec * 8;
        *(float4*)(d + 0) = make_float4(t[0], t[1], t[2], t[3]);
        *(float4*)(d + 4) = make_float4(t[4], t[5], t[6], t[7]);
    }
    __syncwarp();

    if (!valid) return;

    if (f < 0) {
        out[i] = make_float4(bg[0], bg[1], bg[2], 0.0f);
        return;
    }

    // Read my record (7x LDS.128, conflict-free: stride 36 words)
    float a[28];
    #pragma unroll
    for (int j = 0; j < 7; j++) {
        float4 t = *(const float4*)(ws + lane * 36 + 4*j);
        a[4*j+0] = t.x; a[4*j+1] = t.y; a[4*j+2] = t.z; a[4*j+3] = t.w;
    }

    float px = b0*a[0] + b1*a[ 9] + b2*a[18];
    float py = b0*a[1] + b1*a[10] + b2*a[19];
    float pz = b0*a[2] + b1*a[11] + b2*a[20];

    float nx = b0*a[3] + b1*a[12] + b2*a[21];
    float ny = b0*a[4] + b1*a[13] + b2*a[22];
    float nz = b0*a[5] + b1*a[14] + b2*a[23];

    float tr = b0*a[6] + b1*a[15] + b2*a[24];
    float tg = b0*a[7] + b1*a[16] + b2*a[25];
    float tb = b0*a[8] + b1*a[17] + b2*a[26];

    shade_and_store(px, py, pz, nx, ny, nz, tr, tg, tb,
                    lloc[3*nb+0], lloc[3*nb+1], lloc[3*nb+2],
                    cam[3*nb+0],  cam[3*nb+1],  cam[3*nb+2],
                    l_amb, l_dif, l_spec, m_amb, m_dif, m_spec,
                    shin[0], &out[i]);
}

// ---------------------------------------------------------------------------
// Fallback path (mesh exceeds static scratch): direct gathers.
// ---------------------------------------------------------------------------
__global__ __launch_bounds__(256) void shade_direct_kernel(
    const int*   __restrict__ p2f,
    const float* __restrict__ bary,
    const float* __restrict__ verts,
    const float* __restrict__ vnorm,
    const float* __restrict__ vcol,
    const int*   __restrict__ faces,
    const float* __restrict__ lloc,
    const float* __restrict__ l_amb,
    const float* __restrict__ l_dif,
    const float* __restrict__ l_spec,
    const float* __restrict__ m_amb,
    const float* __restrict__ m_dif,
    const float* __restrict__ m_spec,
    const float* __restrict__ shin,
    const float* __restrict__ cam,
    const float* __restrict__ bg,
    float4*      __restrict__ out,
    int HW)
{
    int pix = blockIdx.x * blockDim.x + threadIdx.x;
    if (pix >= HW) return;
    int nb = blockIdx.y;
    int i  = nb * HW + pix;

    int f = p2f[i];
    if (f < 0) {
        out[i] = make_float4(bg[0], bg[1], bg[2], 0.0f);
        return;
    }

    float b0 = bary[3*i + 0];
    float b1 = bary[3*i + 1];
    float b2 = bary[3*i + 2];

    int v0 = faces[3*f + 0];
    int v1 = faces[3*f + 1];
    int v2 = faces[3*f + 2];

    float px = b0*verts[3*v0+0] + b1*verts[3*v1+0] + b2*verts[3*v2+0];
    float py = b0*verts[3*v0+1] + b1*verts[3*v1+1] + b2*verts[3*v2+1];
    float pz = b0*verts[3*v0+2] + b1*verts[3*v1+2] + b2*verts[3*v2+2];

    float nx = b0*vnorm[3*v0+0] + b1*vnorm[3*v1+0] + b2*vnorm[3*v2+0];
    float ny = b0*vnorm[3*v0+1] + b1*vnorm[3*v1+1] + b2*vnorm[3*v2+1];
    float nz = b0*vnorm[3*v0+2] + b1*vnorm[3*v1+2] + b2*vnorm[3*v2+2];

    float tr = b0*vcol[3*v0+0] + b1*vcol[3*v1+0] + b2*vcol[3*v2+0];
    float tg = b0*vcol[3*v0+1] + b1*vcol[3*v1+1] + b2*vcol[3*v2+1];
    float tb = b0*vcol[3*v0+2] + b1*vcol[3*v1+2] + b2*vcol[3*v2+2];

    shade_and_store(px, py, pz, nx, ny, nz, tr, tg, tb,
                    lloc[3*nb+0], lloc[3*nb+1], lloc[3*nb+2],
                    cam[3*nb+0],  cam[3*nb+1],  cam[3*nb+2],
                    l_amb, l_dif, l_spec, m_amb, m_dif, m_spec,
                    shin[0], &out[i]);
}

extern "C" void kernel_launch(void* const* d_in, const int* in_sizes, int n_in,
                              void* d_out, int out_size) {
    const int*   p2f    = (const int*)  d_in[0];
    const float* bary   = (const float*)d_in[1];
    const float* verts  = (const float*)d_in[2];
    const float* vnorm  = (const float*)d_in[3];
    const float* vcol   = (const float*)d_in[4];
    const int*   faces  = (const int*)  d_in[5];
    const float* lloc   = (const float*)d_in[6];
    const float* l_amb  = (const float*)d_in[7];
    const float* l_dif  = (const float*)d_in[8];
    const float* l_spec = (const float*)d_in[9];
    const float* m_amb  = (const float*)d_in[10];
    const float* m_dif  = (const float*)d_in[11];
    const float* m_spec = (const float*)d_in[12];
    const float* shin   = (const float*)d_in[13];
    const float* cam    = (const float*)d_in[14];
    const float* bg     = (const float*)d_in[15];

    int total = in_sizes[0];          // N*H*W*K, K=1
    int N     = in_sizes[6] / 3;      // light_location is (N,3)
    int HW    = total / N;
    int F     = in_sizes[5] / 3;      // faces is (F,3)
    int V     = in_sizes[2] / 3;      // verts is (V,3)

    int threads = 256;
    dim3 grid((HW + threads - 1) / threads, N);

    if (F <= MAX_FACES && V <= MAX_VERTS) {
        pack_verts_kernel<<<(V + threads - 1) / threads, threads>>>(
            verts, vnorm, vcol, V);
        pack_faces_kernel<<<(F + threads - 1) / threads, threads>>>(faces, F);
        shade_packed_kernel<<<grid, threads>>>(
            p2f, bary, lloc,
            l_amb, l_dif, l_spec, m_amb, m_dif, m_spec, shin, cam, bg,
            (float4*)d_out, HW);
    } else {
        shade_direct_kernel<<<grid, threads>>>(
            p2f, bary, verts, vnorm, vcol, faces, lloc,
            l_amb, l_dif, l_spec, m_amb, m_dif, m_spec, shin, cam, bg,
            (float4*)d_out, HW);
    }
}

// round 11
// speedup vs baseline: 1.4140x; 1.0101x over previous
#include <cuda_runtime.h>
#include <cuda_bf16.h>

#define EPS 1e-6f

// ---------------------------------------------------------------------------
// Scratch (static __device__ arrays; no allocation).
// g_vtx:    per-vertex record, 16 floats (64 B): pos(3) nrm(3) col(3) pad(7)
// g_packed: per-face record, 32 floats (128 B = 1 line): corner-major,
//           corner k at offset 9k: pos(3) nrm(3) col(3); floats 27..31 pad
// ---------------------------------------------------------------------------
#define MAX_FACES 204800
#define MAX_VERTS 131072
__device__ __align__(128) float g_packed[(size_t)MAX_FACES * 32];
__device__ __align__(128) float g_vtx[(size_t)MAX_VERTS * 16];

// 256-bit load (Blackwell LDG.E.256). Requires 32B-aligned address.
__device__ __forceinline__ void ldg256(const float* __restrict__ p, float* r) {
    asm volatile("ld.global.nc.v8.f32 {%0,%1,%2,%3,%4,%5,%6,%7}, [%8];"
        : "=f"(r[0]), "=f"(r[1]), "=f"(r[2]), "=f"(r[3]),
          "=f"(r[4]), "=f"(r[5]), "=f"(r[6]), "=f"(r[7])
        : "l"(p));
}

// ---------------------------------------------------------------------------
// Stage 1: pack vertices. Block stages 256 vertices' worth of each attribute
// array via coalesced float4 loads into smem, then writes 64B records.
// ---------------------------------------------------------------------------
__global__ __launch_bounds__(256) void pack_verts_kernel(
    const float* __restrict__ verts,
    const float* __restrict__ vnorm,
    const float* __restrict__ vcol,
    int V)
{
    __shared__ float sp[768], sn[768], sc[768];
    int t  = threadIdx.x;
    int v0 = blockIdx.x * 256;

    if (v0 + 256 <= V) {
        // full block: 3 arrays x 192 float4 = 576 chunks over 256 threads
        const float4* vp = (const float4*)(verts + (size_t)v0 * 3);
        const float4* np = (const float4*)(vnorm + (size_t)v0 * 3);
        const float4* cp = (const float4*)(vcol  + (size_t)v0 * 3);
        #pragma unroll
        for (int c = t; c < 576; c += 256) {
            int arr = c / 192;
            int idx = c - arr * 192;
            float4 val = (arr == 0) ? vp[idx] : (arr == 1) ? np[idx] : cp[idx];
            float* dst = (arr == 0) ? sp : (arr == 1) ? sn : sc;
            *(float4*)(dst + 4 * idx) = val;
        }
        __syncthreads();

        int v = v0 + t;
        float4* o = (float4*)(g_vtx + (size_t)v * 16);
        o[0] = make_float4(sp[3*t+0], sp[3*t+1], sp[3*t+2], sn[3*t+0]);
        o[1] = make_float4(sn[3*t+1], sn[3*t+2], sc[3*t+0], sc[3*t+1]);
        o[2] = make_float4(sc[3*t+2], 0.f, 0.f, 0.f);
    } else {
        // tail block: scalar path
        int v = v0 + t;
        if (v >= V) return;
        float4* o = (float4*)(g_vtx + (size_t)v * 16);
        o[0] = make_float4(verts[3*v+0], verts[3*v+1], verts[3*v+2], vnorm[3*v+0]);
        o[1] = make_float4(vnorm[3*v+1], vnorm[3*v+2], vcol[3*v+0], vcol[3*v+1]);
        o[2] = make_float4(vcol[3*v+2], 0.f, 0.f, 0.f);
    }
}

// ---------------------------------------------------------------------------
// Stage 2: pack faces. One thread per face, 6x LDG.256 from vertex records,
// output via smem staging -> fully coalesced 16B-chunk stores.
// ---------------------------------------------------------------------------
__global__ __launch_bounds__(256) void pack_faces_kernel(
    const int* __restrict__ faces,
    int F)
{
    __shared__ float s[256 * 36];
    int f0 = blockIdx.x * 256;
    int f  = f0 + threadIdx.x;

    float r[32];
    if (f < F) {
        int v0 = faces[3*f + 0];
        int v1 = faces[3*f + 1];
        int v2 = faces[3*f + 2];
        float t[16];
        ldg256(g_vtx + (size_t)v0*16,     t);
        ldg256(g_vtx + (size_t)v0*16 + 8, t + 8);
        #pragma unroll
        for (int k = 0; k < 9; k++) r[k] = t[k];
        ldg256(g_vtx + (size_t)v1*16,     t);
        ldg256(g_vtx + (size_t)v1*16 + 8, t + 8);
        #pragma unroll
        for (int k = 0; k < 9; k++) r[9 + k] = t[k];
        ldg256(g_vtx + (size_t)v2*16,     t);
        ldg256(g_vtx + (size_t)v2*16 + 8, t + 8);
        #pragma unroll
        for (int k = 0; k < 9; k++) r[18 + k] = t[k];
        #pragma unroll
        for (int k = 27; k < 32; k++) r[k] = 0.0f;
    } else {
        #pragma unroll
        for (int k = 0; k < 32; k++) r[k] = 0.0f;
    }

    #pragma unroll
    for (int j = 0; j < 8; j++)
        *(float4*)(s + threadIdx.x * 36 + 4*j) =
            make_float4(r[4*j+0], r[4*j+1], r[4*j+2], r[4*j+3]);
    __syncthreads();

    float4* gout = (float4*)(g_packed + (size_t)f0 * 32);
    #pragma unroll
    for (int p = 0; p < 8; p++) {
        int c   = p * 256 + threadIdx.x;
        int rec = c >> 3;
        int off = c & 7;
        gout[c] = *(const float4*)(s + rec * 36 + 4 * off);
    }
}

// ---------------------------------------------------------------------------
// Shading math
// ---------------------------------------------------------------------------
__device__ __forceinline__ void shade_and_store(
    float px, float py, float pz,
    float nx, float ny, float nz,
    float tr, float tg, float tb,
    float lx, float ly, float lz,
    float cx, float cy, float cz,
    const float* __restrict__ l_amb, const float* __restrict__ l_dif,
    const float* __restrict__ l_spec, const float* __restrict__ m_amb,
    const float* __restrict__ m_dif,  const float* __restrict__ m_spec,
    float sh, float4* outp)
{
    {
        float nn  = sqrtf(nx*nx + ny*ny + nz*nz);
        float inv = 1.0f / fmaxf(nn, EPS);
        nx *= inv; ny *= inv; nz *= inv;
    }
    float tlx = lx - px, tly = ly - py, tlz = lz - pz;
    {
        float nn  = sqrtf(tlx*tlx + tly*tly + tlz*tlz);
        float inv = 1.0f / fmaxf(nn, EPS);
        tlx *= inv; tly *= inv; tlz *= inv;
    }
    float cosang = nx*tlx + ny*tly + nz*tlz;
    float dmax   = fmaxf(cosang, 0.0f);

    float spec = 0.0f;
    if (cosang > 0.0f) {
        float vx = cx - px, vy = cy - py, vz = cz - pz;
        float nn  = sqrtf(vx*vx + vy*vy + vz*vz);
        float inv = 1.0f / fmaxf(nn, EPS);
        vx *= inv; vy *= inv; vz *= inv;

        float c2 = 2.0f * cosang;
        float rx = c2*nx - tlx;
        float ry = c2*ny - tly;
        float rz = c2*nz - tlz;

        float alpha = fmaxf(vx*rx + vy*ry + vz*rz, 0.0f);
        if (alpha > 0.0f)
            spec = __powf(alpha, sh);
    }

    float cr = (m_amb[0]*l_amb[0] + m_dif[0]*l_dif[0]*dmax) * tr + m_spec[0]*l_spec[0]*spec;
    float cg = (m_amb[1]*l_amb[1] + m_dif[1]*l_dif[1]*dmax) * tg + m_spec[1]*l_spec[1]*spec;
    float cb = (m_amb[2]*l_amb[2] + m_dif[2]*l_dif[2]*dmax) * tb + m_spec[2]*l_spec[2]*spec;

    *outp = make_float4(cr, cg, cb, 1.0f);
}

// ---------------------------------------------------------------------------
// Shade: WARP-LOCAL cooperative gather. Each warp stages its own 32 records
// (4 lanes x LDG.256 per record, face idx via shfl) into a private smem
// slice; only __syncwarp() needed. 48 independent warps/SM hide L2 latency.
// ---------------------------------------------------------------------------
__global__ __launch_bounds__(256) void shade_packed_kernel(
    const int*   __restrict__ p2f,
    const float* __restrict__ bary,
    const float* __restrict__ lloc,
    const float* __restrict__ l_amb,
    const float* __restrict__ l_dif,
    const float* __restrict__ l_spec,
    const float* __restrict__ m_amb,
    const float* __restrict__ m_dif,
    const float* __restrict__ m_spec,
    const float* __restrict__ shin,
    const float* __restrict__ cam,
    const float* __restrict__ bg,
    float4*      __restrict__ out,
    int HW)
{
    __shared__ float s[256 * 36];

    int tid  = threadIdx.x;
    int lane = tid & 31;
    int pix  = blockIdx.x * 256 + tid;
    int nb   = blockIdx.y;
    int i    = nb * HW + pix;

    int f = -1;
    float b0 = 0.f, b1 = 0.f, b2 = 0.f;
    bool valid = pix < HW;
    if (valid) {
        f  = p2f[i];
        b0 = bary[3*i + 0];
        b1 = bary[3*i + 1];
        b2 = bary[3*i + 2];
    }
    int frec = (f < 0) ? 0 : f;

    float* ws = s + (tid >> 5) * (32 * 36);   // this warp's smem slice

    // 4 passes: 8 records per pass, 4 lanes per record (one sector each)
    #pragma unroll
    for (int p = 0; p < 4; p++) {
        int slot = p * 8 + (lane >> 2);                     // record slot 0..31
        int rec  = __shfl_sync(0xffffffffu, frec, slot);    // owner's face
        int sec  = lane & 3;
        float t[8];
        ldg256(g_packed + (size_t)rec * 32 + sec * 8, t);
        float* d = ws + slot * 36 + sec * 8;
        *(float4*)(d + 0) = make_float4(t[0], t[1], t[2], t[3]);
        *(float4*)(d + 4) = make_float4(t[4], t[5], t[6], t[7]);
    }
    __syncwarp();

    if (!valid) return;

    if (f < 0) {
        out[i] = make_float4(bg[0], bg[1], bg[2], 0.0f);
        return;
    }

    // Read my record (7x LDS.128, conflict-free: stride 36 words)
    float a[28];
    #pragma unroll
    for (int j = 0; j < 7; j++) {
        float4 t = *(const float4*)(ws + lane * 36 + 4*j);
        a[4*j+0] = t.x; a[4*j+1] = t.y; a[4*j+2] = t.z; a[4*j+3] = t.w;
    }

    float px = b0*a[0] + b1*a[ 9] + b2*a[18];
    float py = b0*a[1] + b1*a[10] + b2*a[19];
    float pz = b0*a[2] + b1*a[11] + b2*a[20];

    float nx = b0*a[3] + b1*a[12] + b2*a[21];
    float ny = b0*a[4] + b1*a[13] + b2*a[22];
    float nz = b0*a[5] + b1*a[14] + b2*a[23];

    float tr = b0*a[6] + b1*a[15] + b2*a[24];
    float tg = b0*a[7] + b1*a[16] + b2*a[25];
    float tb = b0*a[8] + b1*a[17] + b2*a[26];

    shade_and_store(px, py, pz, nx, ny, nz, tr, tg, tb,
                    lloc[3*nb+0], lloc[3*nb+1], lloc[3*nb+2],
                    cam[3*nb+0],  cam[3*nb+1],  cam[3*nb+2],
                    l_amb, l_dif, l_spec, m_amb, m_dif, m_spec,
                    shin[0], &out[i]);
}

// ---------------------------------------------------------------------------
// Fallback path (mesh exceeds static scratch): direct gathers.
// ---------------------------------------------------------------------------
__global__ __launch_bounds__(256) void shade_direct_kernel(
    const int*   __restrict__ p2f,
    const float* __restrict__ bary,
    const float* __restrict__ verts,
    const float* __restrict__ vnorm,
    const float* __restrict__ vcol,
    const int*   __restrict__ faces,
    const float* __restrict__ lloc,
    const float* __restrict__ l_amb,
    const float* __restrict__ l_dif,
    const float* __restrict__ l_spec,
    const float* __restrict__ m_amb,
    const float* __restrict__ m_dif,
    const float* __restrict__ m_spec,
    const float* __restrict__ shin,
    const float* __restrict__ cam,
    const float* __restrict__ bg,
    float4*      __restrict__ out,
    int HW)
{
    int pix = blockIdx.x * blockDim.x + threadIdx.x;
    if (pix >= HW) return;
    int nb = blockIdx.y;
    int i  = nb * HW + pix;

    int f = p2f[i];
    if (f < 0) {
        out[i] = make_float4(bg[0], bg[1], bg[2], 0.0f);
        return;
    }

    float b0 = bary[3*i + 0];
    float b1 = bary[3*i + 1];
    float b2 = bary[3*i + 2];

    int v0 = faces[3*f + 0];
    int v1 = faces[3*f + 1];
    int v2 = faces[3*f + 2];

    float px = b0*verts[3*v0+0] + b1*verts[3*v1+0] + b2*verts[3*v2+0];
    float py = b0*verts[3*v0+1] + b1*verts[3*v1+1] + b2*verts[3*v2+1];
    float pz = b0*verts[3*v0+2] + b1*verts[3*v1+2] + b2*verts[3*v2+2];

    float nx = b0*vnorm[3*v0+0] + b1*vnorm[3*v1+0] + b2*vnorm[3*v2+0];
    float ny = b0*vnorm[3*v0+1] + b1*vnorm[3*v1+1] + b2*vnorm[3*v2+1];
    float nz = b0*vnorm[3*v0+2] + b1*vnorm[3*v1+2] + b2*vnorm[3*v2+2];

    float tr = b0*vcol[3*v0+0] + b1*vcol[3*v1+0] + b2*vcol[3*v2+0];
    float tg = b0*vcol[3*v0+1] + b1*vcol[3*v1+1] + b2*vcol[3*v2+1];
    float tb = b0*vcol[3*v0+2] + b1*vcol[3*v1+2] + b2*vcol[3*v2+2];

    shade_and_store(px, py, pz, nx, ny, nz, tr, tg, tb,
                    lloc[3*nb+0], lloc[3*nb+1], lloc[3*nb+2],
                    cam[3*nb+0],  cam[3*nb+1],  cam[3*nb+2],
                    l_amb, l_dif, l_spec, m_amb, m_dif, m_spec,
                    shin[0], &out[i]);
}

extern "C" void kernel_launch(void* const* d_in, const int* in_sizes, int n_in,
                              void* d_out, int out_size) {
    const int*   p2f    = (const int*)  d_in[0];
    const float* bary   = (const float*)d_in[1];
    const float* verts  = (const float*)d_in[2];
    const float* vnorm  = (const float*)d_in[3];
    const float* vcol   = (const float*)d_in[4];
    const int*   faces  = (const int*)  d_in[5];
    const float* lloc   = (const float*)d_in[6];
    const float* l_amb  = (const float*)d_in[7];
    const float* l_dif  = (const float*)d_in[8];
    const float* l_spec = (const float*)d_in[9];
    const float* m_amb  = (const float*)d_in[10];
    const float* m_dif  = (const float*)d_in[11];
    const float* m_spec = (const float*)d_in[12];
    const float* shin   = (const float*)d_in[13];
    const float* cam    = (const float*)d_in[14];
    const float* bg     = (const float*)d_in[15];

    int total = in_sizes[0];          // N*H*W*K, K=1
    int N     = in_sizes[6] / 3;      // light_location is (N,3)
    int HW    = total / N;
    int F     = in_sizes[5] / 3;      // faces is (F,3)
    int V     = in_sizes[2] / 3;      // verts is (V,3)

    int threads = 256;
    dim3 grid((HW + threads - 1) / threads, N);

    if (F <= MAX_FACES && V <= MAX_VERTS) {
        pack_verts_kernel<<<(V + threads - 1) / threads, threads>>>(
            verts, vnorm, vcol, V);
        pack_faces_kernel<<<(F + threads - 1) / threads, threads>>>(faces, F);
        shade_packed_kernel<<<grid, threads>>>(
            p2f, bary, lloc,
            l_amb, l_dif, l_spec, m_amb, m_dif, m_spec, shin, cam, bg,
            (float4*)d_out, HW);
    } else {
        shade_direct_kernel<<<grid, threads>>>(
            p2f, bary, verts, vnorm, vcol, faces, lloc,
            l_amb, l_dif, l_spec, m_amb, m_dif, m_spec, shin, cam, bg,
            (float4*)d_out, HW);
    }
}